// round 13
// baseline (speedup 1.0000x reference)
#include <cuda_runtime.h>
#include <cuda_fp16.h>
#include <stdint.h>

// ---------------------------------------------------------------------------
// Problem constants: x[32,64,112,112] f32, conv 3x3 pad1 stride1, 64->64 ch.
// ---------------------------------------------------------------------------
#define NB    32
#define CH    64
#define HH_   112
#define WW_   112
#define HW    12544      // 112*112
#define NHW   401408     // 32*112*112
#define NROWS 3584       // 32*112
#define NPAIR 1792
#define NQUAD 896
#define THR   0.6f

// t-row buffer in global: 136 pixels * 64 ci * 2B (fp16), swizzle pre-baked.
#define ROW_PX     136
#define ROW_BYTES  17408            // 136*128
#define ROW_U4     1088             // 17408/16
#define T_BYTES    (NB*HH_*ROW_BYTES)

#define SWZ(o) ((o) ^ (((o) >> 3) & 0x70))

__device__ __align__(16) unsigned char g_t[T_BYTES];
__device__ __align__(16) __half        g_w[9 * 64 * 64];   // swizzled shift tiles
__device__ float  g_csum[NHW];
__device__ float  g_cnum[NHW];
__device__ float2 g_part[CH * NB];
__device__ float  g_sa[CH];     // rstd*gamma
__device__ float  g_sb[CH];     // beta - mean*rstd*gamma

// ---------------------------------------------------------------------------
static __device__ __forceinline__ uint32_t smem_u32(const void* p) {
    uint32_t a;
    asm("{ .reg .u64 t; cvta.to.shared.u64 t, %1; cvt.u32.u64 %0, t; }"
        : "=r"(a) : "l"(p));
    return a;
}
static __device__ __forceinline__ void cp16(uint32_t daddr, const void* g) {
    asm volatile("cp.async.cg.shared.global [%0], [%1], 16;"
                 :: "r"(daddr), "l"(g));
}
#define CP_COMMIT() asm volatile("cp.async.commit_group;" ::: "memory")
#define CP_WAIT0()  asm volatile("cp.async.wait_group 0;" ::: "memory")
#define CP_WAIT1()  asm volatile("cp.async.wait_group 1;" ::: "memory")

// ---------------------------------------------------------------------------
// k0: conv_w [co][ci][kh][kw] f32 -> g_w[s][co][ci] fp16, SW128-swizzled tiles
// ---------------------------------------------------------------------------
__global__ void k_wprep(const float* __restrict__ w) {
    int i = blockIdx.x * blockDim.x + threadIdx.x;
    if (i < 9 * 64 * 64) {
        int co = i / 576;
        int r  = i % 576;
        int ci = r / 9;
        int s  = r % 9;            // kh*3 + kw
        int pos = s * 4096 + (SWZ(co * 128 + ci * 2) >> 1);
        g_w[pos] = __float2half(w[i]);
    }
}

// ---------------------------------------------------------------------------
// k1a: per-(c,n) plane partial sums (float4 loads for MLP)
// ---------------------------------------------------------------------------
__global__ void k_stats1(const float* __restrict__ x) {
    int b = blockIdx.x;
    int c = b >> 5, n = b & 31;
    const float4* xp = (const float4*)(x + (size_t)(n * 64 + c) * HW);
    float s = 0.f, s2 = 0.f;
    for (int i = threadIdx.x; i < HW / 4; i += 256) {
        float4 v = xp[i];
        s  += v.x + v.y + v.z + v.w;
        s2 += v.x * v.x + v.y * v.y + v.z * v.z + v.w * v.w;
    }
    __shared__ float rs[256], rq[256];
    rs[threadIdx.x] = s; rq[threadIdx.x] = s2;
    __syncthreads();
    for (int o = 128; o > 0; o >>= 1) {
        if (threadIdx.x < o) {
            rs[threadIdx.x] += rs[threadIdx.x + o];
            rq[threadIdx.x] += rq[threadIdx.x + o];
        }
        __syncthreads();
    }
    if (threadIdx.x == 0) g_part[c * 32 + n] = make_float2(rs[0], rq[0]);
}

// ---------------------------------------------------------------------------
// k1b: deterministic final reduce -> fused scale/shift
// ---------------------------------------------------------------------------
__global__ void k_stats2(const float* __restrict__ gamma,
                         const float* __restrict__ beta) {
    int c = threadIdx.x;
    if (c < 64) {
        double S = 0.0, S2 = 0.0;
        for (int n = 0; n < 32; n++) {
            float2 p = g_part[c * 32 + n];
            S += (double)p.x; S2 += (double)p.y;
        }
        double m   = S / (double)NHW;
        double var = S2 / (double)NHW - m * m;
        float rstd = (float)(1.0 / sqrt(var + 1e-4));
        float sa = rstd * gamma[c];
        g_sa[c] = sa;
        g_sb[c] = beta[c] - (float)m * sa;
    }
}

// ---------------------------------------------------------------------------
// k2: normalize + ternarize. 256 threads = 2 rows per block. half2 stores.
// ---------------------------------------------------------------------------
__global__ void __launch_bounds__(256)
k_quant(const float* __restrict__ x) {
    __shared__ float sa[64], sb[64];
    __shared__ __half2 st[2 * 112 * 36];   // pitch 36 half2 = 144B
    int tid = threadIdx.x;
    int half = tid >> 7, lt = tid & 127;
    int R = blockIdx.x * 2 + half;
    int n = R / HH_, h = R % HH_;
    if (tid < 64) { sa[tid] = g_sa[tid]; sb[tid] = g_sb[tid]; }
    __syncthreads();
    if (lt < WW_) {
        const float* xp = x + (size_t)n * (64 * HW) + h * WW_ + lt;
        float cs = 0.f, cn = 0.f;
        __half2* so = st + half * (112 * 36) + lt * 36;
        #pragma unroll 8
        for (int ci = 0; ci < 64; ci += 2) {
            float v0 = xp[(size_t)ci * HW];
            float v1 = xp[(size_t)(ci + 1) * HW];
            float x0 = fmaf(v0, sa[ci], sb[ci]);
            float x1 = fmaf(v1, sa[ci + 1], sb[ci + 1]);
            float c0 = fminf(fmaxf(x0, -1.f), 1.f);
            float c1 = fminf(fmaxf(x1, -1.f), 1.f);
            float t0 = (c0 >= THR) ? 1.f : ((c0 <= -THR) ? -1.f : 0.f);
            float t1 = (c1 >= THR) ? 1.f : ((c1 <= -THR) ? -1.f : 0.f);
            cs = fmaf(c0, t0, cs); cs = fmaf(c1, t1, cs);
            cn = fmaf(t0, t0, cn); cn = fmaf(t1, t1, cn);
            so[ci >> 1] = __floats2half2_rn(t0, t1);
        }
        int pi = R * WW_ + lt;
        g_csum[pi] = cs;
        g_cnum[pi] = cn;
    }
    __syncthreads();
    uint4* dst = (uint4*)(g_t + (size_t)R * ROW_BYTES);
    const __half2* sbase = st + half * (112 * 36);
    const uint4 z = make_uint4(0, 0, 0, 0);
    for (int u = lt; u < ROW_U4; u += 128) {
        int bp = u >> 3, cg = u & 7;
        uint4 v = z;
        if (bp >= 1 && bp <= 112)
            v = *(const uint4*)(&sbase[(bp - 1) * 36 + cg * 4]);
        dst[SWZ(u * 16) >> 4] = v;
    }
}

// ---------------------------------------------------------------------------
// k3: PERSISTENT conv, 4 output rows/iter, 512 threads = 16 warps.
//   Warp tile = 32px x 64co (rowsel=wid>>2, wm=wid&3): acc=64 regs/thread,
//   0.375 ldsm/mma (25% less crossbar than 32x32), 4 warps/SMSP retained.
//   8-slot t-row ring, split commit groups; epilogue direct from registers.
// ---------------------------------------------------------------------------
#define BIAS_OFF 0
#define W_OFF    1024
#define RING_OFF (1024 + 73728)                   // 74752
#define BBUF_OFF (RING_OFF + 8 * ROW_BYTES)       // 214016
#define SMEM_TOT (BBUF_OFF + 2048)                // 216064
#define NCTA     148
#define NTHR     512

static __device__ __forceinline__ void ldsm_x4(uint32_t* r, uint32_t addr) {
    asm volatile("ldmatrix.sync.aligned.m8n8.x4.shared.b16 {%0,%1,%2,%3}, [%4];"
                 : "=r"(r[0]), "=r"(r[1]), "=r"(r[2]), "=r"(r[3]) : "r"(addr));
}
static __device__ __forceinline__ void mma16816(float* d, const uint32_t* a,
                                                const uint32_t* b) {
    asm volatile(
        "mma.sync.aligned.m16n8k16.row.col.f32.f16.f16.f32 "
        "{%0,%1,%2,%3}, {%4,%5,%6,%7}, {%8,%9}, {%0,%1,%2,%3};"
        : "+f"(d[0]), "+f"(d[1]), "+f"(d[2]), "+f"(d[3])
        : "r"(a[0]), "r"(a[1]), "r"(a[2]), "r"(a[3]), "r"(b[0]), "r"(b[1]));
}

__global__ void __launch_bounds__(NTHR, 1)
k_conv(const float* __restrict__ convb, const float* __restrict__ bbp,
       float* __restrict__ out) {
    extern __shared__ unsigned char smem[];
    uint32_t sb = smem_u32(smem);
    int tid = threadIdx.x, wid = tid >> 5, lane = tid & 31;

    int P0 = (int)(((long long)blockIdx.x * NQUAD) / NCTA);
    int P1 = (int)(((long long)(blockIdx.x + 1) * NQUAD) / NCTA);

    // Stage weights ONCE (pre-swizzled): 4608 uint4 via cp.async
    for (int i = tid; i < 4608; i += NTHR)
        cp16(sb + W_OFF + i * 16, (const char*)g_w + i * 16);
    if (tid < 64) ((float*)(smem + BIAS_OFF))[tid] = convb[tid];

    // Ring slot for input row r: (r+1) & 7.  r==-1 / r==HH_ -> zero pad;
    // r > HH_ -> skip (never used).
    auto load_row = [&](int nn, int r) {
        if (r > HH_) return;
        uint32_t slot = (uint32_t)(r + 1) & 7u;
        uint32_t dst = sb + RING_OFF + slot * ROW_BYTES;
        if (r < 0 || r >= HH_) {
            uint4 z = make_uint4(0, 0, 0, 0);
            uint4* d = (uint4*)(smem + RING_OFF + slot * ROW_BYTES);
            for (int i = tid; i < ROW_U4; i += NTHR) d[i] = z;
        } else {
            const char* src = (const char*)(g_t + (size_t)(nn * HH_ + r) * ROW_BYTES);
            for (int i = tid; i < ROW_U4; i += NTHR)
                cp16(dst + i * 16, src + i * 16);
        }
    };

    int rowsel = wid >> 2, wm = wid & 3;
    int rA    = wm * 32 + (lane & 15);
    int kaddA = (lane >> 4) * 16;
    int rowB2  = ((lane >> 4) << 3) + (lane & 7);
    int kaddB2 = ((lane >> 3) & 1) * 16;
    int g = lane >> 2, cq = (lane & 3) * 2;
    const float* bias = (const float*)(smem + BIAS_OFF);
    float* bbf = (float*)(smem + BBUF_OFF);   // 4 rows x 128 px
    float bb = bbp[0];
    int r2a = tid >> 7, px = tid & 127;       // beta map: 512 thr = 4 rows

    for (int P = P0; P < P1; P++) {
        int n = P / 28, h = (P % 28) * 4;

        // group1: rows needed THIS iteration
        if (P == P0 || h == 0) {
            load_row(n, h - 1); load_row(n, h);     load_row(n, h + 1);
            load_row(n, h + 2); load_row(n, h + 3); load_row(n, h + 4);
        } else {
            load_row(n, h + 3); load_row(n, h + 4);
        }
        CP_COMMIT();
        // group2: prefetch rows for NEXT iteration (overlap with compute)
        load_row(n, h + 5); load_row(n, h + 6);
        CP_COMMIT();

        // ---- Beta gather (one row per 128-thread group; overlaps wait) ----
        float bs = 0.f, bn = 0.f;
        if (px < WW_) {
            int pi0 = n * HW;
            int hb = h + r2a;
            #pragma unroll
            for (int dh = -1; dh <= 1; dh++) {
                int hh = hb + dh;
                if ((unsigned)hh >= (unsigned)HH_) continue;
                const float* cs = g_csum + pi0 + hh * WW_;
                const float* cn = g_cnum + pi0 + hh * WW_;
                #pragma unroll
                for (int dw = -1; dw <= 1; dw++) {
                    int ww = px + dw;
                    if ((unsigned)ww >= (unsigned)WW_) continue;
                    bs += cs[ww];
                    bn += cn[ww];
                }
            }
        }

        CP_WAIT1();        // group1 landed (group2 still in flight)
        __syncthreads();

        // ---- Compute: 9 shifts x 4 k16 chunks, warp tile 32px x 64co ----
        float acc[2][8][4];
        #pragma unroll
        for (int mt = 0; mt < 2; mt++)
            #pragma unroll
            for (int j = 0; j < 8; j++)
                #pragma unroll
                for (int v = 0; v < 4; v++) acc[mt][j][v] = 0.f;

        #pragma unroll
        for (int s = 0; s < 9; s++) {
            int kh = s / 3, kw = s % 3;
            uint32_t slot = (uint32_t)(h + rowsel + kh) & 7u;  // row h+rowsel-1+kh
            uint32_t abase = sb + RING_OFF + slot * ROW_BYTES;
            uint32_t bbase = sb + W_OFF + s * 8192;
            #pragma unroll
            for (int c = 0; c < 4; c++) {
                uint32_t bf[16];
                #pragma unroll
                for (int q = 0; q < 4; q++) {
                    uint32_t off = (uint32_t)(rowB2 + 16 * q) * 128u
                                 + (uint32_t)c * 32u + kaddB2;
                    ldsm_x4(&bf[q * 4], bbase + SWZ(off));
                }
                uint32_t a[2][4];
                #pragma unroll
                for (int mt = 0; mt < 2; mt++) {
                    uint32_t off = (uint32_t)(rA + mt * 16 + kw) * 128u
                                 + (uint32_t)c * 32u + kaddA;
                    ldsm_x4(a[mt], abase + SWZ(off));
                }
                #pragma unroll
                for (int mt = 0; mt < 2; mt++)
                    #pragma unroll
                    for (int j = 0; j < 8; j++)
                        mma16816(acc[mt][j], a[mt],
                                 &bf[(j >> 1) * 4 + (j & 1) * 2]);
            }
        }

        // ---- Publish per-pixel beta ----
        if (px < WW_) {
            float cnt = bn + bb;
            if (cnt == 0.f) cnt = 1.f;
            bbf[r2a * 128 + px] = (bs + bb) / cnt;
        }
        __syncthreads();

        // ---- Epilogue direct from registers ----
        {
            int row = h + rowsel;
            float* ob = out + (size_t)n * (64 * HW) + row * WW_;
            #pragma unroll
            for (int mt = 0; mt < 2; mt++) {
                int pbase = wm * 32 + mt * 16 + g;
                #pragma unroll
                for (int hf = 0; hf < 2; hf++) {
                    int pp = pbase + hf * 8;
                    if (pp < WW_) {
                        float betav = bbf[rowsel * 128 + pp];
                        #pragma unroll
                        for (int j = 0; j < 8; j++) {
                            int co = j * 8 + cq;
                            ob[(size_t)co * HW + pp] =
                                (acc[mt][j][hf * 2] + bias[co]) * betav;
                            ob[(size_t)(co + 1) * HW + pp] =
                                (acc[mt][j][hf * 2 + 1] + bias[co + 1]) * betav;
                        }
                    }
                }
            }
        }

        CP_WAIT0();        // prefetched rows landed
        __syncthreads();   // ring slots + bbuf reuse visible to all warps
    }
}

// ---------------------------------------------------------------------------
extern "C" void kernel_launch(void* const* d_in, const int* in_sizes, int n_in,
                              void* d_out, int out_size) {
    const float* x     = (const float*)d_in[0];
    const float* gamma = (const float*)d_in[1];
    const float* beta  = (const float*)d_in[2];
    const float* cw    = (const float*)d_in[3];
    const float* cb    = (const float*)d_in[4];
    const float* bb    = (const float*)d_in[5];
    float* out = (float*)d_out;

    cudaFuncSetAttribute(k_conv, cudaFuncAttributeMaxDynamicSharedMemorySize, SMEM_TOT);

    k_wprep<<<288, 128>>>(cw);
    k_stats1<<<2048, 256>>>(x);
    k_stats2<<<1, 64>>>(gamma, beta);
    k_quant<<<NPAIR, 256>>>(x);
    k_conv<<<NCTA, NTHR, SMEM_TOT>>>(cb, bb, out);
}

// round 14
// speedup vs baseline: 1.0769x; 1.0769x over previous
#include <cuda_runtime.h>
#include <cuda_fp16.h>
#include <stdint.h>

// ---------------------------------------------------------------------------
// Problem constants: x[32,64,112,112] f32, conv 3x3 pad1 stride1, 64->64 ch.
// ---------------------------------------------------------------------------
#define NB    32
#define CH    64
#define HH_   112
#define WW_   112
#define HW    12544      // 112*112
#define NHW   401408     // 32*112*112
#define NROWS 3584
#define NPAIR 1792
#define THR   0.6f

// t-row in smem ring: 136 pixels * 64 ci * 2B (fp16), SW128 swizzled.
#define ROW_BYTES  17408            // 136*128
#define ROW_U4     1088

#define SWZ(o) ((o) ^ (((o) >> 3) & 0x70))

__device__ __align__(16) __half g_w[9 * 64 * 64];   // swizzled shift tiles
__device__ float2 g_part[CH * NB];
__device__ float  g_sa[CH];     // rstd*gamma
__device__ float  g_sb[CH];     // beta - mean*rstd*gamma

// ---------------------------------------------------------------------------
static __device__ __forceinline__ uint32_t smem_u32(const void* p) {
    uint32_t a;
    asm("{ .reg .u64 t; cvta.to.shared.u64 t, %1; cvt.u32.u64 %0, t; }"
        : "=r"(a) : "l"(p));
    return a;
}
static __device__ __forceinline__ void cp16(uint32_t daddr, const void* g) {
    asm volatile("cp.async.cg.shared.global [%0], [%1], 16;"
                 :: "r"(daddr), "l"(g));
}
#define CP_COMMIT() asm volatile("cp.async.commit_group;" ::: "memory")
#define CP_WAIT0()  asm volatile("cp.async.wait_group 0;" ::: "memory")

// ---------------------------------------------------------------------------
// k0: conv_w [co][ci][kh][kw] f32 -> g_w[s][co][ci] fp16, SW128-swizzled tiles
// ---------------------------------------------------------------------------
__global__ void k_wprep(const float* __restrict__ w) {
    int i = blockIdx.x * blockDim.x + threadIdx.x;
    if (i < 9 * 64 * 64) {
        int co = i / 576;
        int r  = i % 576;
        int ci = r / 9;
        int s  = r % 9;            // kh*3 + kw
        int pos = s * 4096 + (SWZ(co * 128 + ci * 2) >> 1);
        g_w[pos] = __float2half(w[i]);
    }
}

// ---------------------------------------------------------------------------
// k1a: per-(c,n) plane partial sums (float4 loads for MLP)
// ---------------------------------------------------------------------------
__global__ void k_stats1(const float* __restrict__ x) {
    int b = blockIdx.x;
    int c = b >> 5, n = b & 31;
    const float4* xp = (const float4*)(x + (size_t)(n * 64 + c) * HW);
    float s = 0.f, s2 = 0.f;
    for (int i = threadIdx.x; i < HW / 4; i += 256) {
        float4 v = xp[i];
        s  += v.x + v.y + v.z + v.w;
        s2 += v.x * v.x + v.y * v.y + v.z * v.z + v.w * v.w;
    }
    __shared__ float rs[256], rq[256];
    rs[threadIdx.x] = s; rq[threadIdx.x] = s2;
    __syncthreads();
    for (int o = 128; o > 0; o >>= 1) {
        if (threadIdx.x < o) {
            rs[threadIdx.x] += rs[threadIdx.x + o];
            rq[threadIdx.x] += rq[threadIdx.x + o];
        }
        __syncthreads();
    }
    if (threadIdx.x == 0) g_part[c * 32 + n] = make_float2(rs[0], rq[0]);
}

// ---------------------------------------------------------------------------
// k1b: deterministic final reduce -> fused scale/shift
// ---------------------------------------------------------------------------
__global__ void k_stats2(const float* __restrict__ gamma,
                         const float* __restrict__ beta) {
    int c = threadIdx.x;
    if (c < 64) {
        double S = 0.0, S2 = 0.0;
        for (int n = 0; n < 32; n++) {
            float2 p = g_part[c * 32 + n];
            S += (double)p.x; S2 += (double)p.y;
        }
        double m   = S / (double)NHW;
        double var = S2 / (double)NHW - m * m;
        float rstd = (float)(1.0 / sqrt(var + 1e-4));
        float sa = rstd * gamma[c];
        g_sa[c] = sa;
        g_sb[c] = beta[c] - (float)m * sa;
    }
}

// ---------------------------------------------------------------------------
// k2: FUSED quant + conv, persistent. 148 CTAs, 512 threads, 2 rows/pair.
//   Each CTA quantizes its own rows (incl. halo) straight into the smem
//   ring (no g_t global round-trip); csum/cnum live in small smem rings.
//   Conv: warp tile 32px x 32co (R12 shape), epilogue from registers.
// ---------------------------------------------------------------------------
#define BIAS_OFF 0
#define SA_OFF   256
#define SB_OFF   512
#define CSR_OFF  768                      // 6 x 128 floats
#define CNR_OFF  (CSR_OFF + 3072)         // 3840
#define BBUF_OFF (CNR_OFF + 3072)         // 6912
#define W_OFF    8192                     // 73728 bytes
#define RING_OFF (8192 + 73728)           // 81920 (1024-aligned)
#define SMEM_TOT (RING_OFF + 6 * ROW_BYTES)   // 186368
#define NCTA     148
#define NTHR     512

static __device__ __forceinline__ void ldsm_x4(uint32_t* r, uint32_t addr) {
    asm volatile("ldmatrix.sync.aligned.m8n8.x4.shared.b16 {%0,%1,%2,%3}, [%4];"
                 : "=r"(r[0]), "=r"(r[1]), "=r"(r[2]), "=r"(r[3]) : "r"(addr));
}
static __device__ __forceinline__ void mma16816(float* d, const uint32_t* a,
                                                const uint32_t* b) {
    asm volatile(
        "mma.sync.aligned.m16n8k16.row.col.f32.f16.f16.f32 "
        "{%0,%1,%2,%3}, {%4,%5,%6,%7}, {%8,%9}, {%0,%1,%2,%3};"
        : "+f"(d[0]), "+f"(d[1]), "+f"(d[2]), "+f"(d[3])
        : "r"(a[0]), "r"(a[1]), "r"(a[2]), "r"(a[3]), "r"(b[0]), "r"(b[1]));
}

__global__ void __launch_bounds__(NTHR, 1)
k_conv(const float* __restrict__ x, const float* __restrict__ convb,
       const float* __restrict__ bbp, float* __restrict__ out) {
    extern __shared__ unsigned char smem[];
    uint32_t sb = smem_u32(smem);
    int tid = threadIdx.x, wid = tid >> 5, lane = tid & 31;

    int P0 = (int)(((long long)blockIdx.x * NPAIR) / NCTA);
    int P1 = (int)(((long long)(blockIdx.x + 1) * NPAIR) / NCTA);

    // Stage weights ONCE (pre-swizzled): 4608 uint4 via cp.async
    for (int i = tid; i < 4608; i += NTHR)
        cp16(sb + W_OFF + i * 16, (const char*)g_w + i * 16);
    CP_COMMIT();
    if (tid < 64) {
        ((float*)(smem + BIAS_OFF))[tid] = convb[tid];
        ((float*)(smem + SA_OFF))[tid]   = g_sa[tid];
        ((float*)(smem + SB_OFF))[tid]   = g_sb[tid];
    }
    // Zero entire ring once (padding bp=0 and bp>=113 stays zero forever)
    {
        uint4 z = make_uint4(0, 0, 0, 0);
        uint4* d = (uint4*)(smem + RING_OFF);
        for (int i = tid; i < 6 * ROW_U4; i += NTHR) d[i] = z;
    }
    CP_WAIT0();
    __syncthreads();

    const float* s_sa = (const float*)(smem + SA_OFF);
    const float* s_sb = (const float*)(smem + SB_OFF);
    float* csr = (float*)(smem + CSR_OFF);   // [slot][128]
    float* cnr = (float*)(smem + CNR_OFF);
    float* bbf = (float*)(smem + BBUF_OFF);  // 2 rows x 128 px
    const float* bias = (const float*)(smem + BIAS_OFF);
    float bb = bbp[0];

    int qd = tid & 3, pxp = tid >> 2;        // producer map: 4 thr/px, 16 ci each

    // Quantize row r of image nn into ring slot (r+6)%6 (t + csum/cnum).
    auto produce_row = [&](int nn, int r) {
        uint32_t slot = (uint32_t)(r + 6) % 6u;
        unsigned char* ts = smem + RING_OFF + slot * ROW_BYTES;
        if (r < 0 || r >= HH_) {
            uint4 z = make_uint4(0, 0, 0, 0);
            for (int i = tid; i < 896; i += NTHR) {   // bp 1..112, 8 cg each
                int bp = 1 + (i >> 3), cg = i & 7;
                *(uint4*)(ts + SWZ((uint32_t)(bp * 128 + cg * 16))) = z;
            }
            return;
        }
        if (pxp >= WW_) return;
        const float* xp = x + (size_t)nn * (64 * HW) + (size_t)(qd * 16) * HW
                        + r * WW_ + pxp;
        float v[16];
        #pragma unroll
        for (int i = 0; i < 16; i++) v[i] = xp[(size_t)i * HW];
        float cs = 0.f, cn = 0.f;
        uint32_t h2[8];
        #pragma unroll
        for (int j = 0; j < 8; j++) {
            int c0 = qd * 16 + 2 * j;
            float xn0 = fmaf(v[2 * j],     s_sa[c0],     s_sb[c0]);
            float xn1 = fmaf(v[2 * j + 1], s_sa[c0 + 1], s_sb[c0 + 1]);
            float xc0 = fminf(fmaxf(xn0, -1.f), 1.f);
            float xc1 = fminf(fmaxf(xn1, -1.f), 1.f);
            float t0 = (xc0 >= THR) ? 1.f : ((xc0 <= -THR) ? -1.f : 0.f);
            float t1 = (xc1 >= THR) ? 1.f : ((xc1 <= -THR) ? -1.f : 0.f);
            cs = fmaf(xc0, t0, cs); cs = fmaf(xc1, t1, cs);
            cn = fmaf(t0, t0, cn);  cn = fmaf(t1, t1, cn);
            __half2 hh = __floats2half2_rn(t0, t1);
            h2[j] = *(uint32_t*)&hh;
        }
        cs += __shfl_xor_sync(0xFFFFFFFFu, cs, 1);
        cs += __shfl_xor_sync(0xFFFFFFFFu, cs, 2);
        cn += __shfl_xor_sync(0xFFFFFFFFu, cn, 1);
        cn += __shfl_xor_sync(0xFFFFFFFFu, cn, 2);
        uint32_t off = (uint32_t)(pxp + 1) * 128u + (uint32_t)qd * 32u;
        *(uint4*)(ts + SWZ(off))      = make_uint4(h2[0], h2[1], h2[2], h2[3]);
        *(uint4*)(ts + SWZ(off + 16)) = make_uint4(h2[4], h2[5], h2[6], h2[7]);
        if (qd == 0) {
            csr[slot * 128 + pxp] = cs;
            cnr[slot * 128 + pxp] = cn;
        }
    };

    // Conv fragment maps (R12 shape): 16 warps, tile 32px x 32co
    int rowsel = wid >> 3, wm = (wid >> 1) & 3, wn = wid & 1;
    int rA    = wm * 32 + (lane & 15);
    int kaddA = (lane >> 4) * 16;
    int rowB2  = wn * 32 + ((lane >> 4) << 3) + (lane & 7);
    int kaddB2 = ((lane >> 3) & 1) * 16;
    int g = lane >> 2, cq = (lane & 3) * 2;
    int r2a = (tid >> 7) & 1, px = tid & 127;   // beta map (tid<256 only)

    for (int P = P0; P < P1; P++) {
        int n = P / 56, h = (P % 56) * 2;

        // ---- Produce the new t-rows for this pair ----
        if (P == P0 || h == 0) {
            produce_row(n, h - 1);
            produce_row(n, h);
            produce_row(n, h + 1);
            produce_row(n, h + 2);
        } else {
            produce_row(n, h + 1);
            produce_row(n, h + 2);
        }
        __syncthreads();

        // ---- Beta gather from smem rings ----
        float bs = 0.f, bn = 0.f;
        if (tid < 256 && px < WW_) {
            int hb = h + r2a;
            #pragma unroll
            for (int dh = -1; dh <= 1; dh++) {
                int hh = hb + dh;
                if ((unsigned)hh >= (unsigned)HH_) continue;
                int sl = hh % 6;
                #pragma unroll
                for (int dw = -1; dw <= 1; dw++) {
                    int ww = px + dw;
                    if ((unsigned)ww >= (unsigned)WW_) continue;
                    bs += csr[sl * 128 + ww];
                    bn += cnr[sl * 128 + ww];
                }
            }
        }

        // ---- Compute: 9 shifts x 4 k16 chunks, warp tile 32px x 32co ----
        float acc[2][4][4];
        #pragma unroll
        for (int mt = 0; mt < 2; mt++)
            #pragma unroll
            for (int j = 0; j < 4; j++)
                #pragma unroll
                for (int v = 0; v < 4; v++) acc[mt][j][v] = 0.f;

        #pragma unroll
        for (int s = 0; s < 9; s++) {
            int kh = s / 3, kw = s % 3;
            uint32_t slot = (uint32_t)(h + rowsel + kh + 5) % 6u; // row h+rowsel-1+kh
            uint32_t abase = sb + RING_OFF + slot * ROW_BYTES;
            uint32_t bbase = sb + W_OFF + s * 8192;
            #pragma unroll
            for (int c = 0; c < 4; c++) {
                uint32_t bf[8];
                #pragma unroll
                for (int q = 0; q < 2; q++) {
                    uint32_t off = (uint32_t)(rowB2 + 16 * q) * 128u
                                 + (uint32_t)c * 32u + kaddB2;
                    ldsm_x4(&bf[q * 4], bbase + SWZ(off));
                }
                uint32_t a[2][4];
                #pragma unroll
                for (int mt = 0; mt < 2; mt++) {
                    uint32_t off = (uint32_t)(rA + mt * 16 + kw) * 128u
                                 + (uint32_t)c * 32u + kaddA;
                    ldsm_x4(a[mt], abase + SWZ(off));
                }
                #pragma unroll
                for (int mt = 0; mt < 2; mt++)
                    #pragma unroll
                    for (int j = 0; j < 4; j++)
                        mma16816(acc[mt][j], a[mt],
                                 &bf[(j >> 1) * 4 + (j & 1) * 2]);
            }
        }

        // ---- Publish per-pixel beta ----
        if (tid < 256 && px < WW_) {
            float cnt = bn + bb;
            if (cnt == 0.f) cnt = 1.f;
            bbf[r2a * 128 + px] = (bs + bb) / cnt;
        }
        __syncthreads();

        // ---- Epilogue direct from registers ----
        {
            int row = h + rowsel;
            float* ob = out + (size_t)n * (64 * HW) + row * WW_;
            #pragma unroll
            for (int mt = 0; mt < 2; mt++) {
                int pbase = wm * 32 + mt * 16 + g;
                #pragma unroll
                for (int hf = 0; hf < 2; hf++) {
                    int pp = pbase + hf * 8;
                    if (pp < WW_) {
                        float betav = bbf[rowsel * 128 + pp];
                        #pragma unroll
                        for (int j = 0; j < 4; j++) {
                            int co = wn * 32 + j * 8 + cq;
                            ob[(size_t)co * HW + pp] =
                                (acc[mt][j][hf * 2] + bias[co]) * betav;
                            ob[(size_t)(co + 1) * HW + pp] =
                                (acc[mt][j][hf * 2 + 1] + bias[co + 1]) * betav;
                        }
                    }
                }
            }
        }
        __syncthreads();   // ring/csum/bbuf reuse safe for next production
    }
}

// ---------------------------------------------------------------------------
extern "C" void kernel_launch(void* const* d_in, const int* in_sizes, int n_in,
                              void* d_out, int out_size) {
    const float* x     = (const float*)d_in[0];
    const float* gamma = (const float*)d_in[1];
    const float* beta  = (const float*)d_in[2];
    const float* cw    = (const float*)d_in[3];
    const float* cb    = (const float*)d_in[4];
    const float* bb    = (const float*)d_in[5];
    float* out = (float*)d_out;

    cudaFuncSetAttribute(k_conv, cudaFuncAttributeMaxDynamicSharedMemorySize, SMEM_TOT);

    k_wprep<<<288, 128>>>(cw);
    k_stats1<<<2048, 256>>>(x);
    k_stats2<<<1, 64>>>(gamma, beta);
    k_conv<<<NCTA, NTHR, SMEM_TOT>>>(x, cb, bb, out);
}

// round 15
// speedup vs baseline: 1.0865x; 1.0088x over previous
#include <cuda_runtime.h>
#include <cuda_fp16.h>
#include <stdint.h>

// ---------------------------------------------------------------------------
// Problem constants: x[32,64,112,112] f32, conv 3x3 pad1 stride1, 64->64 ch.
// ---------------------------------------------------------------------------
#define NB    32
#define CH    64
#define HH_   112
#define WW_   112
#define HW    12544      // 112*112
#define NHW   401408     // 32*112*112
#define NROWS 3584
#define NPAIR 1792
#define THR   0.6f

// t-row in smem ring: 136 pixels * 64 ci * 2B (fp16), SW128 swizzled.
#define ROW_BYTES  17408            // 136*128
#define ROW_U4     1088

#define SWZ(o) ((o) ^ (((o) >> 3) & 0x70))

__device__ __align__(16) __half g_w[9 * 64 * 64];   // swizzled shift tiles
__device__ float2 g_part[CH * NB];
__device__ float  g_sa[CH];     // rstd*gamma
__device__ float  g_sb[CH];     // beta - mean*rstd*gamma

// ---------------------------------------------------------------------------
static __device__ __forceinline__ uint32_t smem_u32(const void* p) {
    uint32_t a;
    asm("{ .reg .u64 t; cvta.to.shared.u64 t, %1; cvt.u32.u64 %0, t; }"
        : "=r"(a) : "l"(p));
    return a;
}
static __device__ __forceinline__ void cp16(uint32_t daddr, const void* g) {
    asm volatile("cp.async.cg.shared.global [%0], [%1], 16;"
                 :: "r"(daddr), "l"(g));
}
#define CP_COMMIT() asm volatile("cp.async.commit_group;" ::: "memory")
#define CP_WAIT0()  asm volatile("cp.async.wait_group 0;" ::: "memory")

// ---------------------------------------------------------------------------
// k0: conv_w [co][ci][kh][kw] f32 -> g_w[s][co][ci] fp16, SW128-swizzled tiles
// ---------------------------------------------------------------------------
__global__ void k_wprep(const float* __restrict__ w) {
    int i = blockIdx.x * blockDim.x + threadIdx.x;
    if (i < 9 * 64 * 64) {
        int co = i / 576;
        int r  = i % 576;
        int ci = r / 9;
        int s  = r % 9;            // kh*3 + kw
        int pos = s * 4096 + (SWZ(co * 128 + ci * 2) >> 1);
        g_w[pos] = __float2half(w[i]);
    }
}

// ---------------------------------------------------------------------------
// k1a: per-(c,n) plane partial sums (float4 loads for MLP)
// ---------------------------------------------------------------------------
__global__ void k_stats1(const float* __restrict__ x) {
    int b = blockIdx.x;
    int c = b >> 5, n = b & 31;
    const float4* xp = (const float4*)(x + (size_t)(n * 64 + c) * HW);
    float s = 0.f, s2 = 0.f;
    for (int i = threadIdx.x; i < HW / 4; i += 256) {
        float4 v = xp[i];
        s  += v.x + v.y + v.z + v.w;
        s2 += v.x * v.x + v.y * v.y + v.z * v.z + v.w * v.w;
    }
    __shared__ float rs[256], rq[256];
    rs[threadIdx.x] = s; rq[threadIdx.x] = s2;
    __syncthreads();
    for (int o = 128; o > 0; o >>= 1) {
        if (threadIdx.x < o) {
            rs[threadIdx.x] += rs[threadIdx.x + o];
            rq[threadIdx.x] += rq[threadIdx.x + o];
        }
        __syncthreads();
    }
    if (threadIdx.x == 0) g_part[c * 32 + n] = make_float2(rs[0], rq[0]);
}

// ---------------------------------------------------------------------------
// k1b: deterministic final reduce -> fused scale/shift
// ---------------------------------------------------------------------------
__global__ void k_stats2(const float* __restrict__ gamma,
                         const float* __restrict__ beta) {
    int c = threadIdx.x;
    if (c < 64) {
        double S = 0.0, S2 = 0.0;
        for (int n = 0; n < 32; n++) {
            float2 p = g_part[c * 32 + n];
            S += (double)p.x; S2 += (double)p.y;
        }
        double m   = S / (double)NHW;
        double var = S2 / (double)NHW - m * m;
        float rstd = (float)(1.0 / sqrt(var + 1e-4));
        float sa = rstd * gamma[c];
        g_sa[c] = sa;
        g_sb[c] = beta[c] - (float)m * sa;
    }
}

// ---------------------------------------------------------------------------
// k2: FUSED quant + conv, persistent, SOFTWARE-PIPELINED production.
//   Pair P computes rows h,h+1 from ring rows h-1..h+2 while PRODUCING
//   rows h+3,h+4 (slots disjoint; end-of-iter sync publishes them).
//   Conv: warp tile 32px x 32co (R12 shape), epilogue from registers.
// ---------------------------------------------------------------------------
#define BIAS_OFF 0
#define SA_OFF   256
#define SB_OFF   512
#define CSR_OFF  768                      // 6 x 128 floats
#define CNR_OFF  (CSR_OFF + 3072)         // 3840
#define BBUF_OFF (CNR_OFF + 3072)         // 6912
#define W_OFF    8192                     // 73728 bytes
#define RING_OFF (8192 + 73728)           // 81920 (1024-aligned)
#define SMEM_TOT (RING_OFF + 6 * ROW_BYTES)   // 186368
#define NCTA     148
#define NTHR     512

static __device__ __forceinline__ void ldsm_x4(uint32_t* r, uint32_t addr) {
    asm volatile("ldmatrix.sync.aligned.m8n8.x4.shared.b16 {%0,%1,%2,%3}, [%4];"
                 : "=r"(r[0]), "=r"(r[1]), "=r"(r[2]), "=r"(r[3]) : "r"(addr));
}
static __device__ __forceinline__ void mma16816(float* d, const uint32_t* a,
                                                const uint32_t* b) {
    asm volatile(
        "mma.sync.aligned.m16n8k16.row.col.f32.f16.f16.f32 "
        "{%0,%1,%2,%3}, {%4,%5,%6,%7}, {%8,%9}, {%0,%1,%2,%3};"
        : "+f"(d[0]), "+f"(d[1]), "+f"(d[2]), "+f"(d[3])
        : "r"(a[0]), "r"(a[1]), "r"(a[2]), "r"(a[3]), "r"(b[0]), "r"(b[1]));
}

__global__ void __launch_bounds__(NTHR, 1)
k_conv(const float* __restrict__ x, const float* __restrict__ convb,
       const float* __restrict__ bbp, float* __restrict__ out) {
    extern __shared__ unsigned char smem[];
    uint32_t sb = smem_u32(smem);
    int tid = threadIdx.x, wid = tid >> 5, lane = tid & 31;

    int P0 = (int)(((long long)blockIdx.x * NPAIR) / NCTA);
    int P1 = (int)(((long long)(blockIdx.x + 1) * NPAIR) / NCTA);

    // Stage weights ONCE (pre-swizzled): 4608 uint4 via cp.async
    for (int i = tid; i < 4608; i += NTHR)
        cp16(sb + W_OFF + i * 16, (const char*)g_w + i * 16);
    CP_COMMIT();
    if (tid < 64) {
        ((float*)(smem + BIAS_OFF))[tid] = convb[tid];
        ((float*)(smem + SA_OFF))[tid]   = g_sa[tid];
        ((float*)(smem + SB_OFF))[tid]   = g_sb[tid];
    }
    // Zero entire ring once (padding bp=0 and bp>=113 stays zero forever)
    {
        uint4 z = make_uint4(0, 0, 0, 0);
        uint4* d = (uint4*)(smem + RING_OFF);
        for (int i = tid; i < 6 * ROW_U4; i += NTHR) d[i] = z;
    }
    CP_WAIT0();
    __syncthreads();

    const float* s_sa = (const float*)(smem + SA_OFF);
    const float* s_sb = (const float*)(smem + SB_OFF);
    float* csr = (float*)(smem + CSR_OFF);   // [slot][128]
    float* cnr = (float*)(smem + CNR_OFF);
    float* bbf = (float*)(smem + BBUF_OFF);  // 2 rows x 128 px
    const float* bias = (const float*)(smem + BIAS_OFF);
    float bb = bbp[0];

    int qd = tid & 3, pxp = tid >> 2;        // producer map: 4 thr/px, 16 ci each

    // Quantize row r of image nn into ring slot r%6 (t + csum/cnum).
    auto produce_row = [&](int nn, int r) {
        uint32_t slot = (uint32_t)(r + 6) % 6u;
        unsigned char* ts = smem + RING_OFF + slot * ROW_BYTES;
        if (r < 0 || r >= HH_) {
            uint4 z = make_uint4(0, 0, 0, 0);
            for (int i = tid; i < 896; i += NTHR) {   // bp 1..112, 8 cg each
                int bp = 1 + (i >> 3), cg = i & 7;
                *(uint4*)(ts + SWZ((uint32_t)(bp * 128 + cg * 16))) = z;
            }
            return;
        }
        if (pxp >= WW_) return;
        const float* xp = x + (size_t)nn * (64 * HW) + (size_t)(qd * 16) * HW
                        + r * WW_ + pxp;
        float v[16];
        #pragma unroll
        for (int i = 0; i < 16; i++) v[i] = xp[(size_t)i * HW];
        float cs = 0.f, cn = 0.f;
        uint32_t h2[8];
        #pragma unroll
        for (int j = 0; j < 8; j++) {
            int c0 = qd * 16 + 2 * j;
            float xn0 = fmaf(v[2 * j],     s_sa[c0],     s_sb[c0]);
            float xn1 = fmaf(v[2 * j + 1], s_sa[c0 + 1], s_sb[c0 + 1]);
            float xc0 = fminf(fmaxf(xn0, -1.f), 1.f);
            float xc1 = fminf(fmaxf(xn1, -1.f), 1.f);
            float t0 = (xc0 >= THR) ? 1.f : ((xc0 <= -THR) ? -1.f : 0.f);
            float t1 = (xc1 >= THR) ? 1.f : ((xc1 <= -THR) ? -1.f : 0.f);
            cs = fmaf(xc0, t0, cs); cs = fmaf(xc1, t1, cs);
            cn = fmaf(t0, t0, cn);  cn = fmaf(t1, t1, cn);
            __half2 hh = __floats2half2_rn(t0, t1);
            h2[j] = *(uint32_t*)&hh;
        }
        cs += __shfl_xor_sync(0xFFFFFFFFu, cs, 1);
        cs += __shfl_xor_sync(0xFFFFFFFFu, cs, 2);
        cn += __shfl_xor_sync(0xFFFFFFFFu, cn, 1);
        cn += __shfl_xor_sync(0xFFFFFFFFu, cn, 2);
        uint32_t off = (uint32_t)(pxp + 1) * 128u + (uint32_t)qd * 32u;
        *(uint4*)(ts + SWZ(off))      = make_uint4(h2[0], h2[1], h2[2], h2[3]);
        *(uint4*)(ts + SWZ(off + 16)) = make_uint4(h2[4], h2[5], h2[6], h2[7]);
        if (qd == 0) {
            csr[slot * 128 + pxp] = cs;
            cnr[slot * 128 + pxp] = cn;
        }
    };

    // Conv fragment maps (R12 shape): 16 warps, tile 32px x 32co
    int rowsel = wid >> 3, wm = (wid >> 1) & 3, wn = wid & 1;
    int rA    = wm * 32 + (lane & 15);
    int kaddA = (lane >> 4) * 16;
    int rowB2  = wn * 32 + ((lane >> 4) << 3) + (lane & 7);
    int kaddB2 = ((lane >> 3) & 1) * 16;
    int g = lane >> 2, cq = (lane & 3) * 2;
    int r2a = (tid >> 7) & 1, px = tid & 127;   // beta map (tid<256 only)

    for (int P = P0; P < P1; P++) {
        int n = P / 56, h = (P % 56) * 2;

        // Prime: produce this pair's 4 input rows, then publish.
        if (P == P0 || h == 0) {
            produce_row(n, h - 1);
            produce_row(n, h);
            produce_row(n, h + 1);
            produce_row(n, h + 2);
            __syncthreads();
        }

        // PIPELINED production for the NEXT pair (slots h+3,h+4 are
        // disjoint from this pair's read set h-1..h+2; the end-of-iter
        // sync publishes them). No barrier here -> overlaps with MMA.
        if (P + 1 < P1 && h < HH_ - 2) {
            produce_row(n, h + 3);
            produce_row(n, h + 4);
        }

        // ---- Beta gather from smem rings (rows produced >=1 pair ago) ----
        float bs = 0.f, bn = 0.f;
        if (tid < 256 && px < WW_) {
            int hb = h + r2a;
            #pragma unroll
            for (int dh = -1; dh <= 1; dh++) {
                int hh = hb + dh;
                if ((unsigned)hh >= (unsigned)HH_) continue;
                int sl = hh % 6;
                #pragma unroll
                for (int dw = -1; dw <= 1; dw++) {
                    int ww = px + dw;
                    if ((unsigned)ww >= (unsigned)WW_) continue;
                    bs += csr[sl * 128 + ww];
                    bn += cnr[sl * 128 + ww];
                }
            }
        }

        // ---- Compute: 9 shifts x 4 k16 chunks, warp tile 32px x 32co ----
        float acc[2][4][4];
        #pragma unroll
        for (int mt = 0; mt < 2; mt++)
            #pragma unroll
            for (int j = 0; j < 4; j++)
                #pragma unroll
                for (int v = 0; v < 4; v++) acc[mt][j][v] = 0.f;

        #pragma unroll
        for (int s = 0; s < 9; s++) {
            int kh = s / 3, kw = s % 3;
            uint32_t slot = (uint32_t)(h + rowsel + kh + 5) % 6u; // row h+rowsel-1+kh
            uint32_t abase = sb + RING_OFF + slot * ROW_BYTES;
            uint32_t bbase = sb + W_OFF + s * 8192;
            #pragma unroll
            for (int c = 0; c < 4; c++) {
                uint32_t bf[8];
                #pragma unroll
                for (int q = 0; q < 2; q++) {
                    uint32_t off = (uint32_t)(rowB2 + 16 * q) * 128u
                                 + (uint32_t)c * 32u + kaddB2;
                    ldsm_x4(&bf[q * 4], bbase + SWZ(off));
                }
                uint32_t a[2][4];
                #pragma unroll
                for (int mt = 0; mt < 2; mt++) {
                    uint32_t off = (uint32_t)(rA + mt * 16 + kw) * 128u
                                 + (uint32_t)c * 32u + kaddA;
                    ldsm_x4(a[mt], abase + SWZ(off));
                }
                #pragma unroll
                for (int mt = 0; mt < 2; mt++)
                    #pragma unroll
                    for (int j = 0; j < 4; j++)
                        mma16816(acc[mt][j], a[mt],
                                 &bf[(j >> 1) * 4 + (j & 1) * 2]);
            }
        }

        // ---- Publish per-pixel beta ----
        if (tid < 256 && px < WW_) {
            float cnt = bn + bb;
            if (cnt == 0.f) cnt = 1.f;
            bbf[r2a * 128 + px] = (bs + bb) / cnt;
        }
        __syncthreads();

        // ---- Epilogue direct from registers ----
        {
            int row = h + rowsel;
            float* ob = out + (size_t)n * (64 * HW) + row * WW_;
            #pragma unroll
            for (int mt = 0; mt < 2; mt++) {
                int pbase = wm * 32 + mt * 16 + g;
                #pragma unroll
                for (int hf = 0; hf < 2; hf++) {
                    int pp = pbase + hf * 8;
                    if (pp < WW_) {
                        float betav = bbf[rowsel * 128 + pp];
                        #pragma unroll
                        for (int j = 0; j < 4; j++) {
                            int co = wn * 32 + j * 8 + cq;
                            ob[(size_t)co * HW + pp] =
                                (acc[mt][j][hf * 2] + bias[co]) * betav;
                            ob[(size_t)(co + 1) * HW + pp] =
                                (acc[mt][j][hf * 2 + 1] + bias[co + 1]) * betav;
                        }
                    }
                }
            }
        }
        __syncthreads();   // publish prefetched rows; bbuf/ring reuse safe
    }
}

// ---------------------------------------------------------------------------
extern "C" void kernel_launch(void* const* d_in, const int* in_sizes, int n_in,
                              void* d_out, int out_size) {
    const float* x     = (const float*)d_in[0];
    const float* gamma = (const float*)d_in[1];
    const float* beta  = (const float*)d_in[2];
    const float* cw    = (const float*)d_in[3];
    const float* cb    = (const float*)d_in[4];
    const float* bb    = (const float*)d_in[5];
    float* out = (float*)d_out;

    cudaFuncSetAttribute(k_conv, cudaFuncAttributeMaxDynamicSharedMemorySize, SMEM_TOT);

    k_wprep<<<288, 128>>>(cw);
    k_stats1<<<2048, 256>>>(x);
    k_stats2<<<1, 64>>>(gamma, beta);
    k_conv<<<NCTA, NTHR, SMEM_TOT>>>(x, cb, bb, out);
}

// round 16
// speedup vs baseline: 1.1073x; 1.0192x over previous
#include <cuda_runtime.h>
#include <cuda_fp16.h>
#include <stdint.h>

// ---------------------------------------------------------------------------
// Problem constants: x[32,64,112,112] f32, conv 3x3 pad1 stride1, 64->64 ch.
// ---------------------------------------------------------------------------
#define NB    32
#define CH    64
#define HH_   112
#define WW_   112
#define HW    12544      // 112*112
#define NHW   401408     // 32*112*112
#define NPAIR 1792
#define THR   0.6f

// t-row in smem ring: 136 pixels * 64 ci * 2B (fp16), SW128 swizzled.
#define ROW_BYTES  17408            // 136*128
#define ROW_U4     1088

#define SWZ(o) ((o) ^ (((o) >> 3) & 0x70))

__device__ __align__(16) __half g_w[9 * 64 * 64];   // swizzled shift tiles
__device__ float2 g_part[CH * NB];
__device__ float  g_sa[CH];     // rstd*gamma
__device__ float  g_sb[CH];     // beta - mean*rstd*gamma

// ---------------------------------------------------------------------------
static __device__ __forceinline__ uint32_t smem_u32(const void* p) {
    uint32_t a;
    asm("{ .reg .u64 t; cvta.to.shared.u64 t, %1; cvt.u32.u64 %0, t; }"
        : "=r"(a) : "l"(p));
    return a;
}
static __device__ __forceinline__ void cp16(uint32_t daddr, const void* g) {
    asm volatile("cp.async.cg.shared.global [%0], [%1], 16;"
                 :: "r"(daddr), "l"(g));
}
#define CP_COMMIT() asm volatile("cp.async.commit_group;" ::: "memory")
#define CP_WAIT0()  asm volatile("cp.async.wait_group 0;" ::: "memory")

// ---------------------------------------------------------------------------
// k0: conv_w [co][ci][kh][kw] f32 -> g_w[s][co][ci] fp16, SW128-swizzled tiles
// ---------------------------------------------------------------------------
__global__ void k_wprep(const float* __restrict__ w) {
    int i = blockIdx.x * blockDim.x + threadIdx.x;
    if (i < 9 * 64 * 64) {
        int co = i / 576;
        int r  = i % 576;
        int ci = r / 9;
        int s  = r % 9;            // kh*3 + kw
        int pos = s * 4096 + (SWZ(co * 128 + ci * 2) >> 1);
        g_w[pos] = __float2half(w[i]);
    }
}

// ---------------------------------------------------------------------------
// k1a: per-(c,n) plane partial sums (float4 loads for MLP)
// ---------------------------------------------------------------------------
__global__ void k_stats1(const float* __restrict__ x) {
    int b = blockIdx.x;
    int c = b >> 5, n = b & 31;
    const float4* xp = (const float4*)(x + (size_t)(n * 64 + c) * HW);
    float s = 0.f, s2 = 0.f;
    for (int i = threadIdx.x; i < HW / 4; i += 256) {
        float4 v = xp[i];
        s  += v.x + v.y + v.z + v.w;
        s2 += v.x * v.x + v.y * v.y + v.z * v.z + v.w * v.w;
    }
    __shared__ float rs[256], rq[256];
    rs[threadIdx.x] = s; rq[threadIdx.x] = s2;
    __syncthreads();
    for (int o = 128; o > 0; o >>= 1) {
        if (threadIdx.x < o) {
            rs[threadIdx.x] += rs[threadIdx.x + o];
            rq[threadIdx.x] += rq[threadIdx.x + o];
        }
        __syncthreads();
    }
    if (threadIdx.x == 0) g_part[c * 32 + n] = make_float2(rs[0], rq[0]);
}

// ---------------------------------------------------------------------------
// k1b: deterministic final reduce -> fused scale/shift
// ---------------------------------------------------------------------------
__global__ void k_stats2(const float* __restrict__ gamma,
                         const float* __restrict__ beta) {
    int c = threadIdx.x;
    if (c < 64) {
        double S = 0.0, S2 = 0.0;
        for (int n = 0; n < 32; n++) {
            float2 p = g_part[c * 32 + n];
            S += (double)p.x; S2 += (double)p.y;
        }
        double m   = S / (double)NHW;
        double var = S2 / (double)NHW - m * m;
        float rstd = (float)(1.0 / sqrt(var + 1e-4));
        float sa = rstd * gamma[c];
        g_sa[c] = sa;
        g_sb[c] = beta[c] - (float)m * sa;
    }
}

// ---------------------------------------------------------------------------
// k2: FUSED quant + conv, persistent. Production INTERLEAVED with the MMA
//   shift loop (h+3 before s=0..3, h+4 + beta between s=3 and s=4) so
//   production stalls are covered by other warps' HMMA issue.
//   Conv: warp tile 32px x 32co (R12 shape), epilogue from registers.
// ---------------------------------------------------------------------------
#define BIAS_OFF 0
#define SA_OFF   256
#define SB_OFF   512
#define CSR_OFF  768                      // 6 x 128 float2 = 6144 B
#define BBUF_OFF (CSR_OFF + 6144)         // 6912
#define W_OFF    8192                     // 73728 bytes
#define RING_OFF (8192 + 73728)           // 81920 (1024-aligned)
#define SMEM_TOT (RING_OFF + 6 * ROW_BYTES)   // 186368
#define NCTA     148
#define NTHR     512

static __device__ __forceinline__ void ldsm_x4(uint32_t* r, uint32_t addr) {
    asm volatile("ldmatrix.sync.aligned.m8n8.x4.shared.b16 {%0,%1,%2,%3}, [%4];"
                 : "=r"(r[0]), "=r"(r[1]), "=r"(r[2]), "=r"(r[3]) : "r"(addr));
}
static __device__ __forceinline__ void mma16816(float* d, const uint32_t* a,
                                                const uint32_t* b) {
    asm volatile(
        "mma.sync.aligned.m16n8k16.row.col.f32.f16.f16.f32 "
        "{%0,%1,%2,%3}, {%4,%5,%6,%7}, {%8,%9}, {%0,%1,%2,%3};"
        : "+f"(d[0]), "+f"(d[1]), "+f"(d[2]), "+f"(d[3])
        : "r"(a[0]), "r"(a[1]), "r"(a[2]), "r"(a[3]), "r"(b[0]), "r"(b[1]));
}

__global__ void __launch_bounds__(NTHR, 1)
k_conv(const float* __restrict__ x, const float* __restrict__ convb,
       const float* __restrict__ bbp, float* __restrict__ out) {
    extern __shared__ unsigned char smem[];
    uint32_t sb = smem_u32(smem);
    int tid = threadIdx.x, wid = tid >> 5, lane = tid & 31;

    int P0 = (int)(((long long)blockIdx.x * NPAIR) / NCTA);
    int P1 = (int)(((long long)(blockIdx.x + 1) * NPAIR) / NCTA);

    // Stage weights ONCE (pre-swizzled): 4608 uint4 via cp.async
    for (int i = tid; i < 4608; i += NTHR)
        cp16(sb + W_OFF + i * 16, (const char*)g_w + i * 16);
    CP_COMMIT();
    if (tid < 64) {
        ((float*)(smem + BIAS_OFF))[tid] = convb[tid];
        ((float*)(smem + SA_OFF))[tid]   = g_sa[tid];
        ((float*)(smem + SB_OFF))[tid]   = g_sb[tid];
    }
    // Zero entire ring once (padding bp=0 and bp>=113 stays zero forever)
    {
        uint4 z = make_uint4(0, 0, 0, 0);
        uint4* d = (uint4*)(smem + RING_OFF);
        for (int i = tid; i < 6 * ROW_U4; i += NTHR) d[i] = z;
    }
    CP_WAIT0();
    __syncthreads();

    const float* s_sa = (const float*)(smem + SA_OFF);
    const float* s_sb = (const float*)(smem + SB_OFF);
    float2* csr = (float2*)(smem + CSR_OFF);   // [slot][128] (csum, cnum)
    float* bbf = (float*)(smem + BBUF_OFF);    // 2 rows x 128 px
    const float* bias = (const float*)(smem + BIAS_OFF);
    float bb = bbp[0];

    int qd = tid & 3, pxp = tid >> 2;        // producer map: 4 thr/px, 16 ci each

    // Quantize row r of image nn into ring slot (r+6)%6 (t + csum/cnum).
    // Two 8-ci chunks keep the register peak low (acc is live around this).
    auto produce_row = [&](int nn, int r) {
        uint32_t slot = (uint32_t)(r + 6) % 6u;
        unsigned char* ts = smem + RING_OFF + slot * ROW_BYTES;
        if (r < 0 || r >= HH_) {
            uint4 z = make_uint4(0, 0, 0, 0);
            for (int i = tid; i < 896; i += NTHR) {   // bp 1..112, 8 cg each
                int bp = 1 + (i >> 3), cg = i & 7;
                *(uint4*)(ts + SWZ((uint32_t)(bp * 128 + cg * 16))) = z;
            }
            return;
        }
        if (pxp >= WW_) return;
        const float* xp = x + (size_t)nn * (64 * HW) + (size_t)(qd * 16) * HW
                        + r * WW_ + pxp;
        float cs = 0.f, cn = 0.f;
        uint32_t off = (uint32_t)(pxp + 1) * 128u + (uint32_t)qd * 32u;
        #pragma unroll
        for (int chk = 0; chk < 2; chk++) {
            float v[8];
            #pragma unroll
            for (int i = 0; i < 8; i++)
                v[i] = xp[(size_t)(chk * 8 + i) * HW];
            uint32_t h2[4];
            #pragma unroll
            for (int j = 0; j < 4; j++) {
                int c0 = qd * 16 + chk * 8 + 2 * j;
                float xn0 = fmaf(v[2 * j],     s_sa[c0],     s_sb[c0]);
                float xn1 = fmaf(v[2 * j + 1], s_sa[c0 + 1], s_sb[c0 + 1]);
                float xc0 = fminf(fmaxf(xn0, -1.f), 1.f);
                float xc1 = fminf(fmaxf(xn1, -1.f), 1.f);
                float t0 = (xc0 >= THR) ? 1.f : ((xc0 <= -THR) ? -1.f : 0.f);
                float t1 = (xc1 >= THR) ? 1.f : ((xc1 <= -THR) ? -1.f : 0.f);
                cs = fmaf(xc0, t0, cs); cs = fmaf(xc1, t1, cs);
                cn = fmaf(t0, t0, cn);  cn = fmaf(t1, t1, cn);
                __half2 hh = __floats2half2_rn(t0, t1);
                h2[j] = *(uint32_t*)&hh;
            }
            *(uint4*)(ts + SWZ(off + chk * 16)) =
                make_uint4(h2[0], h2[1], h2[2], h2[3]);
        }
        cs += __shfl_xor_sync(0xFFFFFFFFu, cs, 1);
        cs += __shfl_xor_sync(0xFFFFFFFFu, cs, 2);
        cn += __shfl_xor_sync(0xFFFFFFFFu, cn, 1);
        cn += __shfl_xor_sync(0xFFFFFFFFu, cn, 2);
        if (qd == 0) csr[slot * 128 + pxp] = make_float2(cs, cn);
    };

    // Conv fragment maps (R12 shape): 16 warps, tile 32px x 32co
    int rowsel = wid >> 3, wm = (wid >> 1) & 3, wn = wid & 1;
    int rA    = wm * 32 + (lane & 15);
    int kaddA = (lane >> 4) * 16;
    int rowB2  = wn * 32 + ((lane >> 4) << 3) + (lane & 7);
    int kaddB2 = ((lane >> 3) & 1) * 16;
    int g = lane >> 2, cq = (lane & 3) * 2;
    int r2a = (tid >> 7) & 1, px = tid & 127;   // beta map (tid<256 only)

    for (int P = P0; P < P1; P++) {
        int n = P / 56, h = (P % 56) * 2;
        bool pf = (P + 1 < P1) && (h < HH_ - 2);

        // Prime: produce this pair's 4 input rows, then publish.
        if (P == P0 || h == 0) {
            produce_row(n, h - 1);
            produce_row(n, h);
            produce_row(n, h + 1);
            produce_row(n, h + 2);
            __syncthreads();
        }

        float acc[2][4][4];
        #pragma unroll
        for (int mt = 0; mt < 2; mt++)
            #pragma unroll
            for (int j = 0; j < 4; j++)
                #pragma unroll
                for (int v = 0; v < 4; v++) acc[mt][j][v] = 0.f;

        // ---- Interleave 1: produce next-pair row h+3 (no barrier) ----
        if (pf) produce_row(n, h + 3);

        // ---- MMA shifts s = 0..3 ----
        #pragma unroll
        for (int s = 0; s < 4; s++) {
            int kh = s / 3, kw = s % 3;
            uint32_t slot = (uint32_t)(h + rowsel + kh + 5) % 6u;
            uint32_t abase = sb + RING_OFF + slot * ROW_BYTES;
            uint32_t bbase = sb + W_OFF + s * 8192;
            #pragma unroll
            for (int c = 0; c < 4; c++) {
                uint32_t bf[8];
                #pragma unroll
                for (int q = 0; q < 2; q++) {
                    uint32_t off = (uint32_t)(rowB2 + 16 * q) * 128u
                                 + (uint32_t)c * 32u + kaddB2;
                    ldsm_x4(&bf[q * 4], bbase + SWZ(off));
                }
                uint32_t a[2][4];
                #pragma unroll
                for (int mt = 0; mt < 2; mt++) {
                    uint32_t off = (uint32_t)(rA + mt * 16 + kw) * 128u
                                 + (uint32_t)c * 32u + kaddA;
                    ldsm_x4(a[mt], abase + SWZ(off));
                }
                #pragma unroll
                for (int mt = 0; mt < 2; mt++)
                    #pragma unroll
                    for (int j = 0; j < 4; j++)
                        mma16816(acc[mt][j], a[mt],
                                 &bf[(j >> 1) * 4 + (j & 1) * 2]);
            }
        }

        // ---- Interleave 2: produce row h+4 + beta gather ----
        if (pf) produce_row(n, h + 4);

        float bs = 0.f, bn = 0.f;
        if (tid < 256 && px < WW_) {
            int hb = h + r2a;
            #pragma unroll
            for (int dh = -1; dh <= 1; dh++) {
                int hh = hb + dh;
                if ((unsigned)hh >= (unsigned)HH_) continue;
                int sl = hh % 6;
                #pragma unroll
                for (int dw = -1; dw <= 1; dw++) {
                    int ww = px + dw;
                    if ((unsigned)ww >= (unsigned)WW_) continue;
                    float2 v = csr[sl * 128 + ww];
                    bs += v.x;
                    bn += v.y;
                }
            }
        }

        // ---- MMA shifts s = 4..8 ----
        #pragma unroll
        for (int s = 4; s < 9; s++) {
            int kh = s / 3, kw = s % 3;
            uint32_t slot = (uint32_t)(h + rowsel + kh + 5) % 6u;
            uint32_t abase = sb + RING_OFF + slot * ROW_BYTES;
            uint32_t bbase = sb + W_OFF + s * 8192;
            #pragma unroll
            for (int c = 0; c < 4; c++) {
                uint32_t bf[8];
                #pragma unroll
                for (int q = 0; q < 2; q++) {
                    uint32_t off = (uint32_t)(rowB2 + 16 * q) * 128u
                                 + (uint32_t)c * 32u + kaddB2;
                    ldsm_x4(&bf[q * 4], bbase + SWZ(off));
                }
                uint32_t a[2][4];
                #pragma unroll
                for (int mt = 0; mt < 2; mt++) {
                    uint32_t off = (uint32_t)(rA + mt * 16 + kw) * 128u
                                 + (uint32_t)c * 32u + kaddA;
                    ldsm_x4(a[mt], abase + SWZ(off));
                }
                #pragma unroll
                for (int mt = 0; mt < 2; mt++)
                    #pragma unroll
                    for (int j = 0; j < 4; j++)
                        mma16816(acc[mt][j], a[mt],
                                 &bf[(j >> 1) * 4 + (j & 1) * 2]);
            }
        }

        // ---- Publish per-pixel beta ----
        if (tid < 256 && px < WW_) {
            float cnt = bn + bb;
            if (cnt == 0.f) cnt = 1.f;
            bbf[r2a * 128 + px] = (bs + bb) / cnt;
        }
        __syncthreads();

        // ---- Epilogue direct from registers ----
        {
            int row = h + rowsel;
            float* ob = out + (size_t)n * (64 * HW) + row * WW_;
            #pragma unroll
            for (int mt = 0; mt < 2; mt++) {
                int pbase = wm * 32 + mt * 16 + g;
                #pragma unroll
                for (int hf = 0; hf < 2; hf++) {
                    int pp = pbase + hf * 8;
                    if (pp < WW_) {
                        float betav = bbf[rowsel * 128 + pp];
                        #pragma unroll
                        for (int j = 0; j < 4; j++) {
                            int co = wn * 32 + j * 8 + cq;
                            ob[(size_t)co * HW + pp] =
                                (acc[mt][j][hf * 2] + bias[co]) * betav;
                            ob[(size_t)(co + 1) * HW + pp] =
                                (acc[mt][j][hf * 2 + 1] + bias[co + 1]) * betav;
                        }
                    }
                }
            }
        }
        __syncthreads();   // publish produced rows; bbuf/ring reuse safe
    }
}

// ---------------------------------------------------------------------------
extern "C" void kernel_launch(void* const* d_in, const int* in_sizes, int n_in,
                              void* d_out, int out_size) {
    const float* x     = (const float*)d_in[0];
    const float* gamma = (const float*)d_in[1];
    const float* beta  = (const float*)d_in[2];
    const float* cw    = (const float*)d_in[3];
    const float* cb    = (const float*)d_in[4];
    const float* bb    = (const float*)d_in[5];
    float* out = (float*)d_out;

    cudaFuncSetAttribute(k_conv, cudaFuncAttributeMaxDynamicSharedMemorySize, SMEM_TOT);

    k_wprep<<<288, 128>>>(cw);
    k_stats1<<<2048, 256>>>(x);
    k_stats2<<<1, 64>>>(gamma, beta);
    k_conv<<<NCTA, NTHR, SMEM_TOT>>>(x, cb, bb, out);
}